// round 9
// baseline (speedup 1.0000x reference)
#include <cuda_runtime.h>
#include <cuda_bf16.h>
#include <math.h>
#include <stdint.h>

#define NN 20000
#define TT 256
#define EE 320000
#define GG 64
#define CTC 8
#define CPC 16
#define EMB 768
#define NOUT 4
#define FIN 512
#define BN_EPS 1e-5f
#define NBLK ((NN + 255) / 256)

// ---------------- scratch (device globals: allocation-free) ----------------
__device__ float g_h0[(size_t)NN * FIN];
__device__ float g_h1[(size_t)NN * EMB];
__device__ float g_pool[(size_t)GG * EMB];
__device__ float g_cnt[GG];
__device__ __nv_bfloat16 g_ahA[(size_t)NN * EMB];
__device__ __nv_bfloat16 g_alA[(size_t)NN * EMB];
__device__ __nv_bfloat16 g_ahB[(size_t)NN * EMB];
__device__ __nv_bfloat16 g_alB[(size_t)NN * EMB];
__device__ __nv_bfloat16 g_wh[(size_t)EMB * EMB];
__device__ __nv_bfloat16 g_wl[(size_t)EMB * EMB];
__device__ int g_cnt_i[NN];
__device__ int g_rowptr[NN + 1];
__device__ int g_woff[NN];
__device__ int g_csr[EE];
__device__ int g_bsum[NBLK];

// ======================= bf16 split helpers =======================
__device__ __forceinline__ void split1(float v, unsigned short& h, unsigned short& l) {
    __nv_bfloat16 hb = __float2bfloat16(v);
    h = __bfloat16_as_ushort(hb);
    l = __bfloat16_as_ushort(__float2bfloat16(v - __bfloat162float(hb)));
}

// ======================= mma.sync bf16 split GEMM =======================
#define BMT 128
#define BNT 128
#define AH_OFF 0
#define AL_OFF 10240
#define BH_OFF 20480
#define BL_OFF 28672
#define STAGE_BYTES 36864
#define GEMM_SMEM (2 * STAGE_BYTES)

__device__ __forceinline__ uint32_t smem_u32(const void* p) {
    uint32_t a;
    asm("{ .reg .u64 t; cvta.to.shared.u64 t, %1; cvt.u32.u64 %0, t; }" : "=r"(a) : "l"(p));
    return a;
}
__device__ __forceinline__ void ldsm_x4(uint32_t* r, uint32_t addr) {
    asm volatile("ldmatrix.sync.aligned.m8n8.x4.shared.b16 {%0,%1,%2,%3}, [%4];"
                 : "=r"(r[0]), "=r"(r[1]), "=r"(r[2]), "=r"(r[3]) : "r"(addr));
}
__device__ __forceinline__ void ldsm_x4t(uint32_t* r, uint32_t addr) {
    asm volatile("ldmatrix.sync.aligned.m8n8.x4.trans.shared.b16 {%0,%1,%2,%3}, [%4];"
                 : "=r"(r[0]), "=r"(r[1]), "=r"(r[2]), "=r"(r[3]) : "r"(addr));
}
__device__ __forceinline__ void mma_bf16(float* d, const uint32_t* a, const uint32_t* b) {
    asm volatile(
        "mma.sync.aligned.m16n8k16.row.col.f32.bf16.bf16.f32 "
        "{%0,%1,%2,%3}, {%4,%5,%6,%7}, {%8,%9}, {%0,%1,%2,%3};"
        : "+f"(d[0]), "+f"(d[1]), "+f"(d[2]), "+f"(d[3])
        : "r"(a[0]), "r"(a[1]), "r"(a[2]), "r"(a[3]), "r"(b[0]), "r"(b[1]));
}
__device__ __forceinline__ void cpa16(uint32_t dst, const void* src, int sz) {
    asm volatile("cp.async.cg.shared.global [%0], [%1], 16, %2;"
                 :: "r"(dst), "l"(src), "r"(sz) : "memory");
}
__device__ __forceinline__ void cpa_commit() { asm volatile("cp.async.commit_group;" ::: "memory"); }
__device__ __forceinline__ void cpa_wait1() { asm volatile("cp.async.wait_group 1;" ::: "memory"); }
__device__ __forceinline__ void cpa_wait0() { asm volatile("cp.async.wait_group 0;" ::: "memory"); }

// outMode 0: C = act fp32.  1: (Oh,Ol) = hi/lo bf16 of act.  2: atomic pool add.
__global__ __launch_bounds__(256, 2) void gemm_mma_kernel(
    const __nv_bfloat16* __restrict__ Ah, const __nv_bfloat16* __restrict__ Al,
    const __nv_bfloat16* __restrict__ Wh, const __nv_bfloat16* __restrict__ Wl,
    const float* __restrict__ bias, float* __restrict__ C,
    __nv_bfloat16* __restrict__ Oh, __nv_bfloat16* __restrict__ Ol,
    const int* __restrict__ batch, float* __restrict__ pool,
    int M, int K, int Nn, int doRelu, int outMode)
{
    extern __shared__ char smem[];
    const uint32_t sb = smem_u32(smem);
    const int tid = threadIdx.x;
    const int lane = tid & 31;
    const int wid = tid >> 5;
    const int warp_m = wid >> 2;
    const int warp_n = wid & 3;
    const int m0 = blockIdx.y * BMT;
    const int n0 = blockIdx.x * BNT;

    float acc[4][4][4];
#pragma unroll
    for (int i = 0; i < 4; ++i)
#pragma unroll
        for (int j = 0; j < 4; ++j)
#pragma unroll
            for (int q = 0; q < 4; ++q) acc[i][j][q] = 0.f;

    const int nch = K >> 5;

    auto issue = [&](int c, int buf) {
        const uint32_t s0 = sb + (uint32_t)buf * STAGE_BYTES;
        const int kbase = c << 5;
#pragma unroll
        for (int i = 0; i < 2; ++i) {
            const int slot = tid + i * 256;
            {
                const int row = slot >> 2, seg = slot & 3;
                const int m = m0 + row;
                const int sz = (m < M) ? 16 : 0;
                const int mc = (m < M) ? m : (M - 1);
                const char* srcH = (const char*)Ah + ((size_t)mc * K + kbase) * 2 + seg * 16;
                const char* srcL = (const char*)Al + ((size_t)mc * K + kbase) * 2 + seg * 16;
                const uint32_t d = (uint32_t)(row * 80 + seg * 16);
                cpa16(s0 + AH_OFF + d, srcH, sz);
                cpa16(s0 + AL_OFF + d, srcL, sz);
            }
            {
                const int kr = slot >> 4, nseg = slot & 15;
                const uint32_t off = (uint32_t)(kr * 256 + nseg * 16);
                const uint32_t sw = off ^ (((uint32_t)kr & 7u) << 4);
                const char* srcH = (const char*)Wh + ((size_t)(kbase + kr) * Nn + n0) * 2 + nseg * 16;
                const char* srcL = (const char*)Wl + ((size_t)(kbase + kr) * Nn + n0) * 2 + nseg * 16;
                cpa16(s0 + BH_OFF + sw, srcH, 16);
                cpa16(s0 + BL_OFF + sw, srcL, 16);
            }
        }
    };

    issue(0, 0);
    cpa_commit();

    for (int c = 0; c < nch; ++c) {
        if (c + 1 < nch) issue(c + 1, (c + 1) & 1);
        cpa_commit();
        if (c + 1 < nch) cpa_wait1(); else cpa_wait0();
        __syncthreads();

        const uint32_t sbase = sb + (uint32_t)(c & 1) * STAGE_BYTES;
#pragma unroll
        for (int ks = 0; ks < 2; ++ks) {
            uint32_t ahf[4][4], alf[4][4], bbf[4][2];
            const int arow = warp_m * 64 + (lane & 15);
            const int acol = ks * 16 + (lane >> 4) * 8;
#pragma unroll
            for (int mi = 0; mi < 4; ++mi)
                ldsm_x4(ahf[mi], sbase + AH_OFF + (uint32_t)((arow + mi * 16) * 80 + acol * 2));
            const int kr = ks * 16 + (lane & 15);
            const int ncb = warp_n * 32 + (lane >> 4) * 8;
#pragma unroll
            for (int g = 0; g < 2; ++g) {
                const uint32_t off = (uint32_t)(kr * 256 + (ncb + g * 16) * 2);
                const uint32_t sw = off ^ (((uint32_t)kr & 7u) << 4);
                uint32_t r[4];
                ldsm_x4t(r, sbase + BH_OFF + sw);
                bbf[2 * g][0] = r[0]; bbf[2 * g][1] = r[1];
                bbf[2 * g + 1][0] = r[2]; bbf[2 * g + 1][1] = r[3];
            }
#pragma unroll
            for (int mi = 0; mi < 4; ++mi)
#pragma unroll
                for (int nj = 0; nj < 4; ++nj) mma_bf16(acc[mi][nj], ahf[mi], bbf[nj]);
#pragma unroll
            for (int mi = 0; mi < 4; ++mi)
                ldsm_x4(alf[mi], sbase + AL_OFF + (uint32_t)((arow + mi * 16) * 80 + acol * 2));
#pragma unroll
            for (int mi = 0; mi < 4; ++mi)
#pragma unroll
                for (int nj = 0; nj < 4; ++nj) mma_bf16(acc[mi][nj], alf[mi], bbf[nj]);
#pragma unroll
            for (int g = 0; g < 2; ++g) {
                const uint32_t off = (uint32_t)(kr * 256 + (ncb + g * 16) * 2);
                const uint32_t sw = off ^ (((uint32_t)kr & 7u) << 4);
                uint32_t r[4];
                ldsm_x4t(r, sbase + BL_OFF + sw);
                bbf[2 * g][0] = r[0]; bbf[2 * g][1] = r[1];
                bbf[2 * g + 1][0] = r[2]; bbf[2 * g + 1][1] = r[3];
            }
#pragma unroll
            for (int mi = 0; mi < 4; ++mi)
#pragma unroll
                for (int nj = 0; nj < 4; ++nj) mma_bf16(acc[mi][nj], ahf[mi], bbf[nj]);
        }
        __syncthreads();
    }

    // ---- epilogue ----
#pragma unroll
    for (int mi = 0; mi < 4; ++mi) {
#pragma unroll
        for (int nj = 0; nj < 4; ++nj) {
            const int col = n0 + warp_n * 32 + nj * 8 + (lane & 3) * 2;
            const float b0 = bias[col], b1 = bias[col + 1];
#pragma unroll
            for (int half = 0; half < 2; ++half) {
                const int row = m0 + warp_m * 64 + mi * 16 + (lane >> 2) + half * 8;
                if (row >= M) continue;
                float v0 = acc[mi][nj][2 * half] + b0;
                float v1 = acc[mi][nj][2 * half + 1] + b1;
                if (doRelu) { v0 = fmaxf(v0, 0.f); v1 = fmaxf(v1, 0.f); }
                if (outMode == 0) {
                    *(float2*)(C + (size_t)row * Nn + col) = make_float2(v0, v1);
                } else if (outMode == 1) {
                    unsigned short h0v, l0v, h1v, l1v;
                    split1(v0, h0v, l0v);
                    split1(v1, h1v, l1v);
                    *(uint32_t*)(Oh + (size_t)row * Nn + col) = (uint32_t)h0v | ((uint32_t)h1v << 16);
                    *(uint32_t*)(Ol + (size_t)row * Nn + col) = (uint32_t)l0v | ((uint32_t)l1v << 16);
                } else {
                    const int b = batch[row];
                    atomicAdd(&pool[(size_t)b * Nn + col], v0);
                    atomicAdd(&pool[(size_t)b * Nn + col + 1], v1);
                }
            }
        }
    }
}

// ---------------- weight hi/lo split ----------------
__global__ void split_kernel(const float* __restrict__ A,
                             __nv_bfloat16* __restrict__ oh, __nv_bfloat16* __restrict__ ol,
                             int n4)
{
    int i = blockIdx.x * blockDim.x + threadIdx.x;
    if (i >= n4) return;
    float4 v = ((const float4*)A)[i];
    float f[4] = {v.x, v.y, v.z, v.w};
    unsigned short h[4], l[4];
#pragma unroll
    for (int j = 0; j < 4; ++j) split1(f[j], h[j], l[j]);
    uint2 hv, lv;
    hv.x = (uint32_t)h[0] | ((uint32_t)h[1] << 16);
    hv.y = (uint32_t)h[2] | ((uint32_t)h[3] << 16);
    lv.x = (uint32_t)l[0] | ((uint32_t)l[1] << 16);
    lv.y = (uint32_t)l[2] | ((uint32_t)l[3] << 16);
    ((uint2*)oh)[i] = hv;
    ((uint2*)ol)[i] = lv;
}

// ---------------- CSR build (parallel 3-stage scan) ----------------
__global__ void zeroi_kernel(int* __restrict__ p, int n) {
    int i = blockIdx.x * blockDim.x + threadIdx.x;
    if (i < n) p[i] = 0;
}
__global__ void hist_kernel(const int* __restrict__ dst, int* __restrict__ cnt) {
    int e = blockIdx.x * blockDim.x + threadIdx.x;
    if (e < EE) atomicAdd(&cnt[dst[e]], 1);
}
__global__ void reduce_kernel(const int* __restrict__ cnt, int* __restrict__ bsum) {
    __shared__ int tmp[256];
    int i = blockIdx.x * 256 + threadIdx.x;
    tmp[threadIdx.x] = (i < NN) ? cnt[i] : 0;
    __syncthreads();
    for (int off = 128; off > 0; off >>= 1) {
        if (threadIdx.x < off) tmp[threadIdx.x] += tmp[threadIdx.x + off];
        __syncthreads();
    }
    if (threadIdx.x == 0) bsum[blockIdx.x] = tmp[0];
}
__global__ void scanb_kernel(int* __restrict__ bsum) {
    // single thread exclusive scan over NBLK values (tiny)
    if (threadIdx.x == 0) {
        int run = 0;
        for (int i = 0; i < NBLK; ++i) { int v = bsum[i]; bsum[i] = run; run += v; }
    }
}
__global__ void scan2_kernel(const int* __restrict__ cnt, const int* __restrict__ bsum,
                             int* __restrict__ rowptr, int* __restrict__ woff)
{
    __shared__ int tmp[256];
    const int i = blockIdx.x * 256 + threadIdx.x;
    const int v = (i < NN) ? cnt[i] : 0;
    tmp[threadIdx.x] = v;
    __syncthreads();
#pragma unroll
    for (int off = 1; off < 256; off <<= 1) {
        int t = (threadIdx.x >= off) ? tmp[threadIdx.x - off] : 0;
        __syncthreads();
        tmp[threadIdx.x] += t;
        __syncthreads();
    }
    if (i < NN) {
        const int excl = tmp[threadIdx.x] - v + bsum[blockIdx.x];
        rowptr[i] = excl;
        woff[i] = excl;
        if (i == NN - 1) rowptr[NN] = excl + v;
    }
}
__global__ void scatter_kernel(const int* __restrict__ src, const int* __restrict__ dst,
                               int* __restrict__ woff, int* __restrict__ csr)
{
    int e = blockIdx.x * blockDim.x + threadIdx.x;
    if (e >= EE) return;
    int pos = atomicAdd(&woff[dst[e]], 1);
    csr[pos] = src[e];
}

// ---------------- fused gather-agg + self + bf16 split ----------------
__global__ void aggsplit_kernel(const float* __restrict__ h,
                                const int* __restrict__ rowptr, const int* __restrict__ csr,
                                __nv_bfloat16* __restrict__ oh, __nv_bfloat16* __restrict__ ol,
                                int F)
{
    const int n = blockIdx.x;
    const int t = threadIdx.x;  // F/4 threads
    float4 acc = ((const float4*)(h + (size_t)n * F))[t];
    const int beg = rowptr[n], end = rowptr[n + 1];
    int e = beg;
    for (; e + 4 <= end; e += 4) {
        const int s0 = csr[e], s1 = csr[e + 1], s2 = csr[e + 2], s3 = csr[e + 3];
        float4 v0 = __ldg((const float4*)(h + (size_t)s0 * F) + t);
        float4 v1 = __ldg((const float4*)(h + (size_t)s1 * F) + t);
        float4 v2 = __ldg((const float4*)(h + (size_t)s2 * F) + t);
        float4 v3 = __ldg((const float4*)(h + (size_t)s3 * F) + t);
        v0.x += v1.x; v0.y += v1.y; v0.z += v1.z; v0.w += v1.w;
        v2.x += v3.x; v2.y += v3.y; v2.z += v3.z; v2.w += v3.w;
        acc.x += v0.x + v2.x; acc.y += v0.y + v2.y;
        acc.z += v0.z + v2.z; acc.w += v0.w + v2.w;
    }
    for (; e < end; ++e) {
        const int s = csr[e];
        float4 v = __ldg((const float4*)(h + (size_t)s * F) + t);
        acc.x += v.x; acc.y += v.y; acc.z += v.z; acc.w += v.w;
    }
    float f[4] = {acc.x, acc.y, acc.z, acc.w};
    unsigned short hh[4], ll[4];
#pragma unroll
    for (int j = 0; j < 4; ++j) split1(f[j], hh[j], ll[j]);
    uint2 hv, lv;
    hv.x = (uint32_t)hh[0] | ((uint32_t)hh[1] << 16);
    hv.y = (uint32_t)hh[2] | ((uint32_t)hh[3] << 16);
    lv.x = (uint32_t)ll[0] | ((uint32_t)ll[1] << 16);
    lv.y = (uint32_t)ll[2] | ((uint32_t)ll[3] << 16);
    ((uint2*)oh)[(size_t)n * (F >> 2) + t] = hv;
    ((uint2*)ol)[(size_t)n * (F >> 2) + t] = lv;
}

// ---------------- fused temporal conv stack ----------------
__global__ void conv_kernel(const float* __restrict__ x,
                            const float* __restrict__ w0,
                            const float* __restrict__ bn0g, const float* __restrict__ bn0b,
                            const float* __restrict__ bn0m, const float* __restrict__ bn0v,
                            const float* __restrict__ w1,
                            const float* __restrict__ w2,
                            const float* __restrict__ bn2g, const float* __restrict__ bn2b,
                            const float* __restrict__ bn2m, const float* __restrict__ bn2v,
                            float* __restrict__ h0out)
{
    __shared__ float sx[TT];
    __shared__ float s1[TT][CTC + 1];
    __shared__ float s2[TT][CPC + 1];
    __shared__ float sw0[33 * CTC];
    __shared__ float sw1[21 * CTC];
    __shared__ float sw2[CTC * CPC];
    __shared__ float sb0s[CTC], sb0b[CTC], sb2s[CPC], sb2b[CPC];

    const int n = blockIdx.x;
    const int t = threadIdx.x;

    for (int i = t; i < 33 * CTC; i += 256) sw0[i] = w0[i];
    for (int i = t; i < 21 * CTC; i += 256) sw1[i] = w1[i];
    for (int i = t; i < CTC * CPC; i += 256) sw2[i] = w2[i];
    if (t < CTC) {
        float s = bn0g[t] * rsqrtf(bn0v[t] + BN_EPS);
        sb0s[t] = s;
        sb0b[t] = bn0b[t] - bn0m[t] * s;
    }
    if (t < CPC) {
        float s = bn2g[t] * rsqrtf(bn2v[t] + BN_EPS);
        sb2s[t] = s;
        sb2b[t] = bn2b[t] - bn2m[t] * s;
    }
    sx[t] = x[(size_t)n * TT + t];
    __syncthreads();

    float c0[CTC];
#pragma unroll
    for (int c = 0; c < CTC; c++) c0[c] = 0.f;
#pragma unroll 1
    for (int j = 0; j < 33; j++) {
        int tt = t + j - 16;
        float v = (tt >= 0 && tt < TT) ? sx[tt] : 0.f;
#pragma unroll
        for (int c = 0; c < CTC; c++) c0[c] += v * sw0[j * CTC + c];
    }
#pragma unroll
    for (int c = 0; c < CTC; c++) s1[t][c] = c0[c] * sb0s[c] + sb0b[c];
    __syncthreads();

    float d[CTC];
#pragma unroll
    for (int c = 0; c < CTC; c++) d[c] = 0.f;
#pragma unroll 1
    for (int j = 0; j < 21; j++) {
        int tt = t + j - 10;
        if (tt >= 0 && tt < TT) {
#pragma unroll
            for (int c = 0; c < CTC; c++) d[c] += s1[tt][c] * sw1[j * CTC + c];
        }
    }
#pragma unroll
    for (int c = 0; c < CTC; c++) d[c] = fmaxf(d[c], 0.f);

#pragma unroll
    for (int o = 0; o < CPC; o++) {
        float a = 0.f;
#pragma unroll
        for (int c = 0; c < CTC; c++) a += d[c] * sw2[c * CPC + o];
        a = a * sb2s[o] + sb2b[o];
        s2[t][o] = fmaxf(a, 0.f);
    }
    __syncthreads();

    for (int idx = t; idx < 32 * CPC; idx += 256) {
        int tp = idx / CPC, o = idx % CPC;
        float s = 0.f;
#pragma unroll
        for (int p = 0; p < 8; p++) s += s2[tp * 8 + p][o];
        h0out[(size_t)n * FIN + tp * CPC + o] = s * 0.125f;
    }
}

__global__ void zero_kernel(float* __restrict__ p, int n) {
    int i = blockIdx.x * blockDim.x + threadIdx.x;
    if (i < n) p[i] = 0.f;
}

__global__ void cntf_kernel(const int* __restrict__ batch, float* __restrict__ cnt) {
    int i = blockIdx.x * blockDim.x + threadIdx.x;
    if (i < NN) atomicAdd(&cnt[batch[i]], 1.f);
}

__global__ void final_kernel(const float* __restrict__ dw,
                             const float* __restrict__ db,
                             const float* __restrict__ pool,
                             const float* __restrict__ cnt,
                             float* __restrict__ out)
{
    int g = threadIdx.x;
    if (g >= GG) return;
    float c = fmaxf(cnt[g], 1.f);
    float inv = 1.f / c;
    float acc[NOUT];
#pragma unroll
    for (int o = 0; o < NOUT; o++) acc[o] = db[o];
    for (int k = 0; k < EMB; k++) {
        float p = pool[(size_t)g * EMB + k] * inv;
#pragma unroll
        for (int o = 0; o < NOUT; o++) acc[o] += p * dw[k * NOUT + o];
    }
    float m = acc[0];
#pragma unroll
    for (int o = 1; o < NOUT; o++) m = fmaxf(m, acc[o]);
    float s = 0.f;
#pragma unroll
    for (int o = 0; o < NOUT; o++) s += expf(acc[o] - m);
    float lse = m + logf(s);
#pragma unroll
    for (int o = 0; o < NOUT; o++) out[g * NOUT + o] = acc[o] - lse;
}

// ---------------- launch ----------------
extern "C" void kernel_launch(void* const* d_in, const int* in_sizes, int n_in,
                              void* d_out, int out_size)
{
    const float* x       = (const float*)d_in[0];
    const int*   ei      = (const int*)d_in[1];
    const int*   batch   = (const int*)d_in[2];
    const float* conv0_w = (const float*)d_in[3];
    const float* bn0g    = (const float*)d_in[4];
    const float* bn0b    = (const float*)d_in[5];
    const float* bn0m    = (const float*)d_in[6];
    const float* bn0v    = (const float*)d_in[7];
    const float* conv1_w = (const float*)d_in[8];
    const float* conv2_w = (const float*)d_in[9];
    const float* bn2g    = (const float*)d_in[10];
    const float* bn2b    = (const float*)d_in[11];
    const float* bn2m    = (const float*)d_in[12];
    const float* bn2v    = (const float*)d_in[13];
    const float* gin1_w1 = (const float*)d_in[14];
    const float* gin1_b1 = (const float*)d_in[15];
    const float* gin1_w2 = (const float*)d_in[16];
    const float* gin1_b2 = (const float*)d_in[17];
    const float* gin2_w1 = (const float*)d_in[18];
    const float* gin2_b1 = (const float*)d_in[19];
    const float* gin2_w2 = (const float*)d_in[20];
    const float* gin2_b2 = (const float*)d_in[21];
    const float* dense_w = (const float*)d_in[22];
    const float* dense_b = (const float*)d_in[23];
    float* out = (float*)d_out;

    float *h0, *h1, *pool, *cnt;
    __nv_bfloat16 *ahA, *alA, *ahB, *alB, *wh, *wl;
    int *cnti, *rowptr, *woff, *csr, *bsum;
    cudaGetSymbolAddress((void**)&h0,   g_h0);
    cudaGetSymbolAddress((void**)&h1,   g_h1);
    cudaGetSymbolAddress((void**)&pool, g_pool);
    cudaGetSymbolAddress((void**)&cnt,  g_cnt);
    cudaGetSymbolAddress((void**)&ahA,  g_ahA);
    cudaGetSymbolAddress((void**)&alA,  g_alA);
    cudaGetSymbolAddress((void**)&ahB,  g_ahB);
    cudaGetSymbolAddress((void**)&alB,  g_alB);
    cudaGetSymbolAddress((void**)&wh,   g_wh);
    cudaGetSymbolAddress((void**)&wl,   g_wl);
    cudaGetSymbolAddress((void**)&cnti,   g_cnt_i);
    cudaGetSymbolAddress((void**)&rowptr, g_rowptr);
    cudaGetSymbolAddress((void**)&woff,   g_woff);
    cudaGetSymbolAddress((void**)&csr,    g_csr);
    cudaGetSymbolAddress((void**)&bsum,   g_bsum);

    cudaFuncSetAttribute(gemm_mma_kernel, cudaFuncAttributeMaxDynamicSharedMemorySize, GEMM_SMEM);

    const int* src = ei;
    const int* dst = ei + EE;

    // 1. fused temporal conv stack -> h0 (N, 512)
    conv_kernel<<<NN, 256>>>(x, conv0_w, bn0g, bn0b, bn0m, bn0v,
                             conv1_w, conv2_w, bn2g, bn2b, bn2m, bn2v, h0);

    // 2. CSR build (parallel scan)
    zeroi_kernel<<<(NN + 255) / 256, 256>>>(cnti, NN);
    hist_kernel<<<(EE + 255) / 256, 256>>>(dst, cnti);
    reduce_kernel<<<NBLK, 256>>>(cnti, bsum);
    scanb_kernel<<<1, 32>>>(bsum);
    scan2_kernel<<<NBLK, 256>>>(cnti, bsum, rowptr, woff);
    scatter_kernel<<<(EE + 255) / 256, 256>>>(src, dst, woff, csr);

    const dim3 tg(EMB / 128, (NN + 127) / 128);
#define SPLITW(Wsrc, n) split_kernel<<<((n) / 4 + 255) / 256, 256>>>(Wsrc, wh, wl, (n) / 4)

    // 3. GIN layer 1
    aggsplit_kernel<<<NN, FIN / 4>>>(h0, rowptr, csr, ahA, alA, FIN);
    SPLITW(gin1_w1, FIN * EMB);
    gemm_mma_kernel<<<tg, 256, GEMM_SMEM>>>(ahA, alA, wh, wl, gin1_b1,
                                            nullptr, ahB, alB, nullptr, nullptr,
                                            NN, FIN, EMB, 1, 1);
    SPLITW(gin1_w2, EMB * EMB);
    gemm_mma_kernel<<<tg, 256, GEMM_SMEM>>>(ahB, alB, wh, wl, gin1_b2,
                                            h1, nullptr, nullptr, nullptr, nullptr,
                                            NN, EMB, EMB, 1, 0);

    // 4. GIN layer 2
    aggsplit_kernel<<<NN, EMB / 4>>>(h1, rowptr, csr, ahA, alA, EMB);
    SPLITW(gin2_w1, EMB * EMB);
    gemm_mma_kernel<<<tg, 256, GEMM_SMEM>>>(ahA, alA, wh, wl, gin2_b1,
                                            nullptr, ahB, alB, nullptr, nullptr,
                                            NN, EMB, EMB, 1, 1);
    // 5. GEMM4 with fused graph-pool epilogue (atomic adds into pool)
    zero_kernel<<<(GG * EMB + 255) / 256, 256>>>(pool, GG * EMB);
    zero_kernel<<<1, GG>>>(cnt, GG);
    cntf_kernel<<<(NN + 255) / 256, 256>>>(batch, cnt);
    SPLITW(gin2_w2, EMB * EMB);
    gemm_mma_kernel<<<tg, 256, GEMM_SMEM>>>(ahB, alB, wh, wl, gin2_b2,
                                            nullptr, nullptr, nullptr, batch, pool,
                                            NN, EMB, EMB, 1, 2);

    // 6. dense + log_softmax
    final_kernel<<<1, 64>>>(dense_w, dense_b, pool, cnt, out);
}

// round 10
// speedup vs baseline: 1.4922x; 1.4922x over previous
#include <cuda_runtime.h>
#include <cuda_bf16.h>
#include <math.h>
#include <stdint.h>

#define NN 20000
#define TT 256
#define EE 320000
#define GG 64
#define CTC 8
#define CPC 16
#define EMB 768
#define NOUT 4
#define FIN 512
#define BN_EPS 1e-5f
#define NBLK ((NN + 255) / 256)

// ---------------- scratch (device globals: allocation-free) ----------------
__device__ float g_h0[(size_t)NN * FIN];
__device__ float g_h1[(size_t)NN * EMB];
__device__ float g_h2[(size_t)NN * EMB];
__device__ float g_pool[(size_t)GG * EMB];
__device__ float g_cnt[GG];
__device__ __nv_bfloat16 g_ahA[(size_t)NN * EMB];
__device__ __nv_bfloat16 g_alA[(size_t)NN * EMB];
__device__ __nv_bfloat16 g_ahB[(size_t)NN * EMB];
__device__ __nv_bfloat16 g_alB[(size_t)NN * EMB];
__device__ __nv_bfloat16 g_wh[(size_t)EMB * EMB];
__device__ __nv_bfloat16 g_wl[(size_t)EMB * EMB];
__device__ int g_cnt_i[NN];
__device__ int g_rowptr[NN + 1];
__device__ int g_woff[NN];
__device__ int g_csr[EE];
__device__ int g_bsum[NBLK];

// ======================= bf16 split helpers =======================
__device__ __forceinline__ void split1(float v, unsigned short& h, unsigned short& l) {
    __nv_bfloat16 hb = __float2bfloat16(v);
    h = __bfloat16_as_ushort(hb);
    l = __bfloat16_as_ushort(__float2bfloat16(v - __bfloat162float(hb)));
}

// ======================= mma.sync bf16 split GEMM =======================
#define BMT 128
#define BNT 128
#define AH_OFF 0
#define AL_OFF 10240
#define BH_OFF 20480
#define BL_OFF 28672
#define STAGE_BYTES 36864
#define GEMM_SMEM (2 * STAGE_BYTES)

__device__ __forceinline__ uint32_t smem_u32(const void* p) {
    uint32_t a;
    asm("{ .reg .u64 t; cvta.to.shared.u64 t, %1; cvt.u32.u64 %0, t; }" : "=r"(a) : "l"(p));
    return a;
}
__device__ __forceinline__ void ldsm_x4(uint32_t* r, uint32_t addr) {
    asm volatile("ldmatrix.sync.aligned.m8n8.x4.shared.b16 {%0,%1,%2,%3}, [%4];"
                 : "=r"(r[0]), "=r"(r[1]), "=r"(r[2]), "=r"(r[3]) : "r"(addr));
}
__device__ __forceinline__ void ldsm_x4t(uint32_t* r, uint32_t addr) {
    asm volatile("ldmatrix.sync.aligned.m8n8.x4.trans.shared.b16 {%0,%1,%2,%3}, [%4];"
                 : "=r"(r[0]), "=r"(r[1]), "=r"(r[2]), "=r"(r[3]) : "r"(addr));
}
__device__ __forceinline__ void mma_bf16(float* d, const uint32_t* a, const uint32_t* b) {
    asm volatile(
        "mma.sync.aligned.m16n8k16.row.col.f32.bf16.bf16.f32 "
        "{%0,%1,%2,%3}, {%4,%5,%6,%7}, {%8,%9}, {%0,%1,%2,%3};"
        : "+f"(d[0]), "+f"(d[1]), "+f"(d[2]), "+f"(d[3])
        : "r"(a[0]), "r"(a[1]), "r"(a[2]), "r"(a[3]), "r"(b[0]), "r"(b[1]));
}
__device__ __forceinline__ void cpa16(uint32_t dst, const void* src, int sz) {
    asm volatile("cp.async.cg.shared.global [%0], [%1], 16, %2;"
                 :: "r"(dst), "l"(src), "r"(sz) : "memory");
}
__device__ __forceinline__ void cpa_commit() { asm volatile("cp.async.commit_group;" ::: "memory"); }
__device__ __forceinline__ void cpa_wait1() { asm volatile("cp.async.wait_group 1;" ::: "memory"); }
__device__ __forceinline__ void cpa_wait0() { asm volatile("cp.async.wait_group 0;" ::: "memory"); }

// splitOut=0: C = act(A@W+bias) fp32.  splitOut=1: (Oh,Ol) = hi/lo bf16 of act.
__global__ __launch_bounds__(256, 2) void gemm_mma_kernel(
    const __nv_bfloat16* __restrict__ Ah, const __nv_bfloat16* __restrict__ Al,
    const __nv_bfloat16* __restrict__ Wh, const __nv_bfloat16* __restrict__ Wl,
    const float* __restrict__ bias, float* __restrict__ C,
    __nv_bfloat16* __restrict__ Oh, __nv_bfloat16* __restrict__ Ol,
    int M, int K, int Nn, int doRelu, int splitOut)
{
    extern __shared__ char smem[];
    const uint32_t sb = smem_u32(smem);
    const int tid = threadIdx.x;
    const int lane = tid & 31;
    const int wid = tid >> 5;
    const int warp_m = wid >> 2;
    const int warp_n = wid & 3;
    const int m0 = blockIdx.y * BMT;
    const int n0 = blockIdx.x * BNT;

    float acc[4][4][4];
#pragma unroll
    for (int i = 0; i < 4; ++i)
#pragma unroll
        for (int j = 0; j < 4; ++j)
#pragma unroll
            for (int q = 0; q < 4; ++q) acc[i][j][q] = 0.f;

    const int nch = K >> 5;

    auto issue = [&](int c, int buf) {
        const uint32_t s0 = sb + (uint32_t)buf * STAGE_BYTES;
        const int kbase = c << 5;
#pragma unroll
        for (int i = 0; i < 2; ++i) {
            const int slot = tid + i * 256;
            {
                const int row = slot >> 2, seg = slot & 3;
                const int m = m0 + row;
                const int sz = (m < M) ? 16 : 0;
                const int mc = (m < M) ? m : (M - 1);
                const char* srcH = (const char*)Ah + ((size_t)mc * K + kbase) * 2 + seg * 16;
                const char* srcL = (const char*)Al + ((size_t)mc * K + kbase) * 2 + seg * 16;
                const uint32_t d = (uint32_t)(row * 80 + seg * 16);
                cpa16(s0 + AH_OFF + d, srcH, sz);
                cpa16(s0 + AL_OFF + d, srcL, sz);
            }
            {
                const int kr = slot >> 4, nseg = slot & 15;
                const uint32_t off = (uint32_t)(kr * 256 + nseg * 16);
                const uint32_t sw = off ^ (((uint32_t)kr & 7u) << 4);
                const char* srcH = (const char*)Wh + ((size_t)(kbase + kr) * Nn + n0) * 2 + nseg * 16;
                const char* srcL = (const char*)Wl + ((size_t)(kbase + kr) * Nn + n0) * 2 + nseg * 16;
                cpa16(s0 + BH_OFF + sw, srcH, 16);
                cpa16(s0 + BL_OFF + sw, srcL, 16);
            }
        }
    };

    issue(0, 0);
    cpa_commit();

    for (int c = 0; c < nch; ++c) {
        if (c + 1 < nch) issue(c + 1, (c + 1) & 1);
        cpa_commit();
        if (c + 1 < nch) cpa_wait1(); else cpa_wait0();
        __syncthreads();

        const uint32_t sbase = sb + (uint32_t)(c & 1) * STAGE_BYTES;
#pragma unroll
        for (int ks = 0; ks < 2; ++ks) {
            uint32_t ahf[4][4], alf[4][4], bbf[4][2];
            const int arow = warp_m * 64 + (lane & 15);
            const int acol = ks * 16 + (lane >> 4) * 8;
#pragma unroll
            for (int mi = 0; mi < 4; ++mi)
                ldsm_x4(ahf[mi], sbase + AH_OFF + (uint32_t)((arow + mi * 16) * 80 + acol * 2));
            const int kr = ks * 16 + (lane & 15);
            const int ncb = warp_n * 32 + (lane >> 4) * 8;
#pragma unroll
            for (int g = 0; g < 2; ++g) {
                const uint32_t off = (uint32_t)(kr * 256 + (ncb + g * 16) * 2);
                const uint32_t sw = off ^ (((uint32_t)kr & 7u) << 4);
                uint32_t r[4];
                ldsm_x4t(r, sbase + BH_OFF + sw);
                bbf[2 * g][0] = r[0]; bbf[2 * g][1] = r[1];
                bbf[2 * g + 1][0] = r[2]; bbf[2 * g + 1][1] = r[3];
            }
#pragma unroll
            for (int mi = 0; mi < 4; ++mi)
#pragma unroll
                for (int nj = 0; nj < 4; ++nj) mma_bf16(acc[mi][nj], ahf[mi], bbf[nj]);
#pragma unroll
            for (int mi = 0; mi < 4; ++mi)
                ldsm_x4(alf[mi], sbase + AL_OFF + (uint32_t)((arow + mi * 16) * 80 + acol * 2));
#pragma unroll
            for (int mi = 0; mi < 4; ++mi)
#pragma unroll
                for (int nj = 0; nj < 4; ++nj) mma_bf16(acc[mi][nj], alf[mi], bbf[nj]);
#pragma unroll
            for (int g = 0; g < 2; ++g) {
                const uint32_t off = (uint32_t)(kr * 256 + (ncb + g * 16) * 2);
                const uint32_t sw = off ^ (((uint32_t)kr & 7u) << 4);
                uint32_t r[4];
                ldsm_x4t(r, sbase + BL_OFF + sw);
                bbf[2 * g][0] = r[0]; bbf[2 * g][1] = r[1];
                bbf[2 * g + 1][0] = r[2]; bbf[2 * g + 1][1] = r[3];
            }
#pragma unroll
            for (int mi = 0; mi < 4; ++mi)
#pragma unroll
                for (int nj = 0; nj < 4; ++nj) mma_bf16(acc[mi][nj], ahf[mi], bbf[nj]);
        }
        __syncthreads();
    }

    // ---- epilogue ----
#pragma unroll
    for (int mi = 0; mi < 4; ++mi) {
#pragma unroll
        for (int nj = 0; nj < 4; ++nj) {
            const int col = n0 + warp_n * 32 + nj * 8 + (lane & 3) * 2;
            const float b0 = bias[col], b1 = bias[col + 1];
#pragma unroll
            for (int half = 0; half < 2; ++half) {
                const int row = m0 + warp_m * 64 + mi * 16 + (lane >> 2) + half * 8;
                if (row >= M) continue;
                float v0 = acc[mi][nj][2 * half] + b0;
                float v1 = acc[mi][nj][2 * half + 1] + b1;
                if (doRelu) { v0 = fmaxf(v0, 0.f); v1 = fmaxf(v1, 0.f); }
                if (!splitOut) {
                    *(float2*)(C + (size_t)row * Nn + col) = make_float2(v0, v1);
                } else {
                    unsigned short h0v, l0v, h1v, l1v;
                    split1(v0, h0v, l0v);
                    split1(v1, h1v, l1v);
                    *(uint32_t*)(Oh + (size_t)row * Nn + col) = (uint32_t)h0v | ((uint32_t)h1v << 16);
                    *(uint32_t*)(Ol + (size_t)row * Nn + col) = (uint32_t)l0v | ((uint32_t)l1v << 16);
                }
            }
        }
    }
}

// ---------------- weight hi/lo split ----------------
__global__ void split_kernel(const float* __restrict__ A,
                             __nv_bfloat16* __restrict__ oh, __nv_bfloat16* __restrict__ ol,
                             int n4)
{
    int i = blockIdx.x * blockDim.x + threadIdx.x;
    if (i >= n4) return;
    float4 v = ((const float4*)A)[i];
    float f[4] = {v.x, v.y, v.z, v.w};
    unsigned short h[4], l[4];
#pragma unroll
    for (int j = 0; j < 4; ++j) split1(f[j], h[j], l[j]);
    uint2 hv, lv;
    hv.x = (uint32_t)h[0] | ((uint32_t)h[1] << 16);
    hv.y = (uint32_t)h[2] | ((uint32_t)h[3] << 16);
    lv.x = (uint32_t)l[0] | ((uint32_t)l[1] << 16);
    lv.y = (uint32_t)l[2] | ((uint32_t)l[3] << 16);
    ((uint2*)oh)[i] = hv;
    ((uint2*)ol)[i] = lv;
}

// ---------------- CSR build (parallel 3-stage scan) ----------------
__global__ void zeroi_kernel(int* __restrict__ p, int n) {
    int i = blockIdx.x * blockDim.x + threadIdx.x;
    if (i < n) p[i] = 0;
}
__global__ void hist_kernel(const int* __restrict__ dst, int* __restrict__ cnt) {
    int e = blockIdx.x * blockDim.x + threadIdx.x;
    if (e < EE) atomicAdd(&cnt[dst[e]], 1);
}
__global__ void reduce_kernel(const int* __restrict__ cnt, int* __restrict__ bsum) {
    __shared__ int tmp[256];
    int i = blockIdx.x * 256 + threadIdx.x;
    tmp[threadIdx.x] = (i < NN) ? cnt[i] : 0;
    __syncthreads();
    for (int off = 128; off > 0; off >>= 1) {
        if (threadIdx.x < off) tmp[threadIdx.x] += tmp[threadIdx.x + off];
        __syncthreads();
    }
    if (threadIdx.x == 0) bsum[blockIdx.x] = tmp[0];
}
__global__ void scanb_kernel(int* __restrict__ bsum) {
    if (threadIdx.x == 0) {
        int run = 0;
        for (int i = 0; i < NBLK; ++i) { int v = bsum[i]; bsum[i] = run; run += v; }
    }
}
__global__ void scan2_kernel(const int* __restrict__ cnt, const int* __restrict__ bsum,
                             int* __restrict__ rowptr, int* __restrict__ woff)
{
    __shared__ int tmp[256];
    const int i = blockIdx.x * 256 + threadIdx.x;
    const int v = (i < NN) ? cnt[i] : 0;
    tmp[threadIdx.x] = v;
    __syncthreads();
#pragma unroll
    for (int off = 1; off < 256; off <<= 1) {
        int t = (threadIdx.x >= off) ? tmp[threadIdx.x - off] : 0;
        __syncthreads();
        tmp[threadIdx.x] += t;
        __syncthreads();
    }
    if (i < NN) {
        const int excl = tmp[threadIdx.x] - v + bsum[blockIdx.x];
        rowptr[i] = excl;
        woff[i] = excl;
        if (i == NN - 1) rowptr[NN] = excl + v;
    }
}
__global__ void scatter_kernel(const int* __restrict__ src, const int* __restrict__ dst,
                               int* __restrict__ woff, int* __restrict__ csr)
{
    int e = blockIdx.x * blockDim.x + threadIdx.x;
    if (e >= EE) return;
    int pos = atomicAdd(&woff[dst[e]], 1);
    csr[pos] = src[e];
}

// ---------------- fused gather-agg + self + bf16 split ----------------
__global__ void aggsplit_kernel(const float* __restrict__ h,
                                const int* __restrict__ rowptr, const int* __restrict__ csr,
                                __nv_bfloat16* __restrict__ oh, __nv_bfloat16* __restrict__ ol,
                                int F)
{
    const int n = blockIdx.x;
    const int t = threadIdx.x;  // F/4 threads
    float4 acc = ((const float4*)(h + (size_t)n * F))[t];
    const int beg = rowptr[n], end = rowptr[n + 1];
    int e = beg;
    for (; e + 4 <= end; e += 4) {
        const int s0 = csr[e], s1 = csr[e + 1], s2 = csr[e + 2], s3 = csr[e + 3];
        float4 v0 = __ldg((const float4*)(h + (size_t)s0 * F) + t);
        float4 v1 = __ldg((const float4*)(h + (size_t)s1 * F) + t);
        float4 v2 = __ldg((const float4*)(h + (size_t)s2 * F) + t);
        float4 v3 = __ldg((const float4*)(h + (size_t)s3 * F) + t);
        v0.x += v1.x; v0.y += v1.y; v0.z += v1.z; v0.w += v1.w;
        v2.x += v3.x; v2.y += v3.y; v2.z += v3.z; v2.w += v3.w;
        acc.x += v0.x + v2.x; acc.y += v0.y + v2.y;
        acc.z += v0.z + v2.z; acc.w += v0.w + v2.w;
    }
    for (; e < end; ++e) {
        const int s = csr[e];
        float4 v = __ldg((const float4*)(h + (size_t)s * F) + t);
        acc.x += v.x; acc.y += v.y; acc.z += v.z; acc.w += v.w;
    }
    float f[4] = {acc.x, acc.y, acc.z, acc.w};
    unsigned short hh[4], ll[4];
#pragma unroll
    for (int j = 0; j < 4; ++j) split1(f[j], hh[j], ll[j]);
    uint2 hv, lv;
    hv.x = (uint32_t)hh[0] | ((uint32_t)hh[1] << 16);
    hv.y = (uint32_t)hh[2] | ((uint32_t)hh[3] << 16);
    lv.x = (uint32_t)ll[0] | ((uint32_t)ll[1] << 16);
    lv.y = (uint32_t)ll[2] | ((uint32_t)ll[3] << 16);
    ((uint2*)oh)[(size_t)n * (F >> 2) + t] = hv;
    ((uint2*)ol)[(size_t)n * (F >> 2) + t] = lv;
}

// ---------------- fused temporal conv stack ----------------
__global__ void conv_kernel(const float* __restrict__ x,
                            const float* __restrict__ w0,
                            const float* __restrict__ bn0g, const float* __restrict__ bn0b,
                            const float* __restrict__ bn0m, const float* __restrict__ bn0v,
                            const float* __restrict__ w1,
                            const float* __restrict__ w2,
                            const float* __restrict__ bn2g, const float* __restrict__ bn2b,
                            const float* __restrict__ bn2m, const float* __restrict__ bn2v,
                            float* __restrict__ h0out)
{
    __shared__ float sx[TT];
    __shared__ float s1[TT][CTC + 1];
    __shared__ float s2[TT][CPC + 1];
    __shared__ float sw0[33 * CTC];
    __shared__ float sw1[21 * CTC];
    __shared__ float sw2[CTC * CPC];
    __shared__ float sb0s[CTC], sb0b[CTC], sb2s[CPC], sb2b[CPC];

    const int n = blockIdx.x;
    const int t = threadIdx.x;

    for (int i = t; i < 33 * CTC; i += 256) sw0[i] = w0[i];
    for (int i = t; i < 21 * CTC; i += 256) sw1[i] = w1[i];
    for (int i = t; i < CTC * CPC; i += 256) sw2[i] = w2[i];
    if (t < CTC) {
        float s = bn0g[t] * rsqrtf(bn0v[t] + BN_EPS);
        sb0s[t] = s;
        sb0b[t] = bn0b[t] - bn0m[t] * s;
    }
    if (t < CPC) {
        float s = bn2g[t] * rsqrtf(bn2v[t] + BN_EPS);
        sb2s[t] = s;
        sb2b[t] = bn2b[t] - bn2m[t] * s;
    }
    sx[t] = x[(size_t)n * TT + t];
    __syncthreads();

    float c0[CTC];
#pragma unroll
    for (int c = 0; c < CTC; c++) c0[c] = 0.f;
#pragma unroll 1
    for (int j = 0; j < 33; j++) {
        int tt = t + j - 16;
        float v = (tt >= 0 && tt < TT) ? sx[tt] : 0.f;
#pragma unroll
        for (int c = 0; c < CTC; c++) c0[c] += v * sw0[j * CTC + c];
    }
#pragma unroll
    for (int c = 0; c < CTC; c++) s1[t][c] = c0[c] * sb0s[c] + sb0b[c];
    __syncthreads();

    float d[CTC];
#pragma unroll
    for (int c = 0; c < CTC; c++) d[c] = 0.f;
#pragma unroll 1
    for (int j = 0; j < 21; j++) {
        int tt = t + j - 10;
        if (tt >= 0 && tt < TT) {
#pragma unroll
            for (int c = 0; c < CTC; c++) d[c] += s1[tt][c] * sw1[j * CTC + c];
        }
    }
#pragma unroll
    for (int c = 0; c < CTC; c++) d[c] = fmaxf(d[c], 0.f);

#pragma unroll
    for (int o = 0; o < CPC; o++) {
        float a = 0.f;
#pragma unroll
        for (int c = 0; c < CTC; c++) a += d[c] * sw2[c * CPC + o];
        a = a * sb2s[o] + sb2b[o];
        s2[t][o] = fmaxf(a, 0.f);
    }
    __syncthreads();

    for (int idx = t; idx < 32 * CPC; idx += 256) {
        int tp = idx / CPC, o = idx % CPC;
        float s = 0.f;
#pragma unroll
        for (int p = 0; p < 8; p++) s += s2[tp * 8 + p][o];
        h0out[(size_t)n * FIN + tp * CPC + o] = s * 0.125f;
    }
}

__global__ void zero_kernel(float* __restrict__ p, int n) {
    int i = blockIdx.x * blockDim.x + threadIdx.x;
    if (i < n) p[i] = 0.f;
}

__global__ void pool_kernel(const float* __restrict__ h,
                            const int* __restrict__ batch,
                            float* __restrict__ pool, float* __restrict__ cnt)
{
    int n = blockIdx.x;
    int b = batch[n];
    for (int f = threadIdx.x; f < EMB; f += blockDim.x)
        atomicAdd(&pool[(size_t)b * EMB + f], h[(size_t)n * EMB + f]);
    if (threadIdx.x == 0) atomicAdd(&cnt[b], 1.f);
}

__global__ void final_kernel(const float* __restrict__ dw,
                             const float* __restrict__ db,
                             const float* __restrict__ pool,
                             const float* __restrict__ cnt,
                             float* __restrict__ out)
{
    int g = threadIdx.x;
    if (g >= GG) return;
    float c = fmaxf(cnt[g], 1.f);
    float inv = 1.f / c;
    float acc[NOUT];
#pragma unroll
    for (int o = 0; o < NOUT; o++) acc[o] = db[o];
    for (int k = 0; k < EMB; k++) {
        float p = pool[(size_t)g * EMB + k] * inv;
#pragma unroll
        for (int o = 0; o < NOUT; o++) acc[o] += p * dw[k * NOUT + o];
    }
    float m = acc[0];
#pragma unroll
    for (int o = 1; o < NOUT; o++) m = fmaxf(m, acc[o]);
    float s = 0.f;
#pragma unroll
    for (int o = 0; o < NOUT; o++) s += expf(acc[o] - m);
    float lse = m + logf(s);
#pragma unroll
    for (int o = 0; o < NOUT; o++) out[g * NOUT + o] = acc[o] - lse;
}

// ---------------- launch ----------------
extern "C" void kernel_launch(void* const* d_in, const int* in_sizes, int n_in,
                              void* d_out, int out_size)
{
    const float* x       = (const float*)d_in[0];
    const int*   ei      = (const int*)d_in[1];
    const int*   batch   = (const int*)d_in[2];
    const float* conv0_w = (const float*)d_in[3];
    const float* bn0g    = (const float*)d_in[4];
    const float* bn0b    = (const float*)d_in[5];
    const float* bn0m    = (const float*)d_in[6];
    const float* bn0v    = (const float*)d_in[7];
    const float* conv1_w = (const float*)d_in[8];
    const float* conv2_w = (const float*)d_in[9];
    const float* bn2g    = (const float*)d_in[10];
    const float* bn2b    = (const float*)d_in[11];
    const float* bn2m    = (const float*)d_in[12];
    const float* bn2v    = (const float*)d_in[13];
    const float* gin1_w1 = (const float*)d_in[14];
    const float* gin1_b1 = (const float*)d_in[15];
    const float* gin1_w2 = (const float*)d_in[16];
    const float* gin1_b2 = (const float*)d_in[17];
    const float* gin2_w1 = (const float*)d_in[18];
    const float* gin2_b1 = (const float*)d_in[19];
    const float* gin2_w2 = (const float*)d_in[20];
    const float* gin2_b2 = (const float*)d_in[21];
    const float* dense_w = (const float*)d_in[22];
    const float* dense_b = (const float*)d_in[23];
    float* out = (float*)d_out;

    float *h0, *h1, *h2, *pool, *cnt;
    __nv_bfloat16 *ahA, *alA, *ahB, *alB, *wh, *wl;
    int *cnti, *rowptr, *woff, *csr, *bsum;
    cudaGetSymbolAddress((void**)&h0,   g_h0);
    cudaGetSymbolAddress((void**)&h1,   g_h1);
    cudaGetSymbolAddress((void**)&h2,   g_h2);
    cudaGetSymbolAddress((void**)&pool, g_pool);
    cudaGetSymbolAddress((void**)&cnt,  g_cnt);
    cudaGetSymbolAddress((void**)&ahA,  g_ahA);
    cudaGetSymbolAddress((void**)&alA,  g_alA);
    cudaGetSymbolAddress((void**)&ahB,  g_ahB);
    cudaGetSymbolAddress((void**)&alB,  g_alB);
    cudaGetSymbolAddress((void**)&wh,   g_wh);
    cudaGetSymbolAddress((void**)&wl,   g_wl);
    cudaGetSymbolAddress((void**)&cnti,   g_cnt_i);
    cudaGetSymbolAddress((void**)&rowptr, g_rowptr);
    cudaGetSymbolAddress((void**)&woff,   g_woff);
    cudaGetSymbolAddress((void**)&csr,    g_csr);
    cudaGetSymbolAddress((void**)&bsum,   g_bsum);

    cudaFuncSetAttribute(gemm_mma_kernel, cudaFuncAttributeMaxDynamicSharedMemorySize, GEMM_SMEM);

    const int* src = ei;
    const int* dst = ei + EE;

    // 1. fused temporal conv stack -> h0 (N, 512)
    conv_kernel<<<NN, 256>>>(x, conv0_w, bn0g, bn0b, bn0m, bn0v,
                             conv1_w, conv2_w, bn2g, bn2b, bn2m, bn2v, h0);

    // 2. CSR build (parallel scan)
    zeroi_kernel<<<(NN + 255) / 256, 256>>>(cnti, NN);
    hist_kernel<<<(EE + 255) / 256, 256>>>(dst, cnti);
    reduce_kernel<<<NBLK, 256>>>(cnti, bsum);
    scanb_kernel<<<1, 32>>>(bsum);
    scan2_kernel<<<NBLK, 256>>>(cnti, bsum, rowptr, woff);
    scatter_kernel<<<(EE + 255) / 256, 256>>>(src, dst, woff, csr);

    const dim3 tg(EMB / 128, (NN + 127) / 128);
#define SPLITW(Wsrc, n) split_kernel<<<((n) / 4 + 255) / 256, 256>>>(Wsrc, wh, wl, (n) / 4)

    // 3. GIN layer 1
    aggsplit_kernel<<<NN, FIN / 4>>>(h0, rowptr, csr, ahA, alA, FIN);
    SPLITW(gin1_w1, FIN * EMB);
    gemm_mma_kernel<<<tg, 256, GEMM_SMEM>>>(ahA, alA, wh, wl, gin1_b1,
                                            nullptr, ahB, alB, NN, FIN, EMB, 1, 1);
    SPLITW(gin1_w2, EMB * EMB);
    gemm_mma_kernel<<<tg, 256, GEMM_SMEM>>>(ahB, alB, wh, wl, gin1_b2,
                                            h1, nullptr, nullptr, NN, EMB, EMB, 1, 0);

    // 4. GIN layer 2
    aggsplit_kernel<<<NN, EMB / 4>>>(h1, rowptr, csr, ahA, alA, EMB);
    SPLITW(gin2_w1, EMB * EMB);
    gemm_mma_kernel<<<tg, 256, GEMM_SMEM>>>(ahA, alA, wh, wl, gin2_b1,
                                            nullptr, ahB, alB, NN, EMB, EMB, 1, 1);
    SPLITW(gin2_w2, EMB * EMB);
    gemm_mma_kernel<<<tg, 256, GEMM_SMEM>>>(ahB, alB, wh, wl, gin2_b2,
                                            h2, nullptr, nullptr, NN, EMB, EMB, 1, 0);

    // 5. per-graph mean pool + dense + log_softmax
    zero_kernel<<<(GG * EMB + 255) / 256, 256>>>(pool, GG * EMB);
    zero_kernel<<<1, GG>>>(cnt, GG);
    pool_kernel<<<NN, 256>>>(h2, batch, pool, cnt);
    final_kernel<<<1, 64>>>(dense_w, dense_b, pool, cnt, out);
}